// round 17
// baseline (speedup 1.0000x reference)
#include <cuda_runtime.h>

// Problem constants (fixed by reference hparams)
#define BB     32          // batch
#define NSEG   108         // MAX_NUM_SEG
#define NTOT   3456        // BB*NSEG
#define SS     64          // candidates per segment
#define TX     2560        // MAX_LEN_PAD
#define D4     20          // feature dim / 4 (float4 units)
#define MINSEG 19
#define OUTROWS (BB * TX)  // 81920 output rows
#define NQUAD  (OUTROWS * D4)   // 1,638,400 output float4s
#define NCHUNK (NQUAD / 512)    // 3200 chunks of 512 float4s
#define PGRID  1184             // persistent gather grid: 148 SMs x 8 blocks
#define MAXCH  3                // ceil(3200/1184) chunks per block

// Scratch (no allocations allowed -> __device__ globals)
__device__ int4 g_seginfo[NTOT];    // {local_base, cnt, off, scale_bits}
__device__ int  g_btot[BB];         // per-batch count totals
__device__ int2 g_meta2[OUTROWS];   // per OUTPUT row: {src_row, lam} or {-1,0}

// ---------------------------------------------------------------------------
// shfl exclusive warp scan; returns exclusive prefix, sets warp total
// ---------------------------------------------------------------------------
__device__ __forceinline__ int warp_excl(int v, int lane, int& tot) {
    int x = v;
#pragma unroll
    for (int o = 1; o < 32; o <<= 1) {
        int y = __shfl_up_sync(0xffffffffu, x, o);
        if (lane >= o) x += y;
    }
    tot = __shfl_sync(0xffffffffu, x, 31);
    return x - v;
}

// Masked count for one segment: #{ s in [0,64) : floor(rn(s/scale)) < L }.
// Estimate seed + exact __fdiv_rn verification -> bit-exact vs reference.
__device__ __forceinline__ int seg_cnt(int len, int lseq, int off, float scale) {
    const int L = min(len - 1, lseq - 1 - off);
    if (L <= 0) return 0;
    const float Lf = (float)L;
    int s = (int)(Lf * scale);             // seed near the boundary
    if (s > 63) s = 63;
    while (s > 0 && !(floorf(__fdiv_rn((float)s, scale)) < Lf)) s--;
    while (s < 63 && (floorf(__fdiv_rn((float)(s + 1), scale)) < Lf)) s++;
    return s + 1;                          // cond(0) true since L>0
}

// ---------------------------------------------------------------------------
// Kernel 1: one WARP per batch (32 blocks x 32 threads), zero barriers.
// Triggers PDL completion at entry so k_rowmeta's dispatch overlaps this body.
// ---------------------------------------------------------------------------
__global__ void __launch_bounds__(32) k_seg(const int* __restrict__ len_seq,
                                            const float* __restrict__ scales_u,
                                            const int* __restrict__ len_seg_raw) {
    cudaTriggerProgrammaticLaunchCompletion();   // let consumers start dispatch

    const int b = blockIdx.x;
    const int lane = threadIdx.x;
    const bool act = lane < NSEG / 4;      // 27 active lanes

    int4 lr = make_int4(-MINSEG, -MINSEG, -MINSEG, -MINSEG);
    float4 sc = make_float4(0.5f, 0.5f, 0.5f, 0.5f);
    const int vidx = b * (NSEG / 4) + lane;
    if (act) {
        lr = ((const int4*)len_seg_raw)[vidx];
        sc = ((const float4*)scales_u)[vidx];
    }
    const int lseq = len_seq[b];

    const int l0 = lr.x + MINSEG, l1 = lr.y + MINSEG;
    const int l2 = lr.z + MINSEG, l3 = lr.w + MINSEG;
    const float s0 = sc.x + 0.5f, s1 = sc.y + 0.5f;
    const float s2 = sc.z + 0.5f, s3 = sc.w + 0.5f;

    // scan #1: len_seg -> offsets
    int tot;
    const int ex = warp_excl(l0 + l1 + l2 + l3, lane, tot);
    const int o0 = ex, o1 = ex + l0, o2 = o1 + l1, o3 = o2 + l2;

    // counts (ILP across 4 segments)
    const int c0 = seg_cnt(l0, lseq, o0, s0);
    const int c1 = seg_cnt(l1, lseq, o1, s1);
    const int c2 = seg_cnt(l2, lseq, o2, s2);
    const int c3 = seg_cnt(l3, lseq, o3, s3);

    // scan #2: counts -> local bases + batch total
    int ctot;
    const int cex = warp_excl(c0 + c1 + c2 + c3, lane, ctot);

    if (act) {
        const int n0 = b * NSEG + lane * 4;
        g_seginfo[n0 + 0] = make_int4(cex,                c0, o0, __float_as_int(s0));
        g_seginfo[n0 + 1] = make_int4(cex + c0,           c1, o1, __float_as_int(s1));
        g_seginfo[n0 + 2] = make_int4(cex + c0 + c1,      c2, o2, __float_as_int(s2));
        g_seginfo[n0 + 3] = make_int4(cex + c0 + c1 + c2, c3, o3, __float_as_int(s3));
    }
    if (lane == 0) g_btot[b] = ctot;
}

// ---------------------------------------------------------------------------
// Kernel 2: scatter metadata DIRECTLY into output-row order.
//   meta2[b_out*TX + t] = {src_row, lam}  for valid rows (t < rows)
//   meta2[b_out*TX + t] = {-1, 0}         for padding   (t in [rows, TX))
// Per-warp prologue: each warp loads g_btot[lane] (one 128B L2 line),
// shfl-scans it, extracts its batch base + rows. No smem, no barriers.
// ---------------------------------------------------------------------------
__global__ void __launch_bounds__(256) k_rowmeta() {
    cudaTriggerProgrammaticLaunchCompletion();   // let gather start dispatch

    const int tid = threadIdx.x;
    const int lane = tid & 31;
    const int n = blockIdx.x * 8 + (tid >> 5);   // this warp's segment
    const int bsrc = n / NSEG;                   // source batch (warp-uniform)

    cudaGridDependencySynchronize();             // wait: k_seg outputs visible

    // per-warp cross-batch scan: lane k carries batch k's total
    int gtot;
    const int gex = warp_excl(g_btot[lane], lane, gtot);
    const int rows = gtot / BB;
    const int bbase = __shfl_sync(0xffffffffu, gex, bsrc);  // base of batch bsrc

    const int4 si = g_seginfo[n];        // {local_base, cnt, off, scale_bits}
    const int cnt = si.y;
    if (cnt > 0 && rows > 0) {
        const int base  = bbase + si.x;           // absolute compacted base
        const int off   = si.z;
        const float scale = __int_as_float(si.w);
        const int bTX   = bsrc * TX;              // SOURCE batch row base

        for (int s = lane; s < cnt; s += 32) {    // cnt <= 64 -> <= 2 iters
            const float v  = __fdiv_rn((float)s, scale);
            const float fl = floorf(v);
            const float lam = v - fl;
            int i = (int)fl + off;                // exact small ints
            if (i > TX - 2) i = TX - 2;
            if (i < 0) i = 0;

            const int p = base + s;
            const int b_out = p / rows;           // output batch of position p
            const int t = p - b_out * rows;
            if (t < TX && b_out < BB)             // rows>TX or tail overflow
                g_meta2[b_out * TX + t] = make_int2(bTX + i, __float_as_int(lam));
        }
    }

    // ---- padding fill: grid-stride over the complement region ----
    const int padh = (rows < TX) ? (TX - rows) : 0;   // padding per batch
    const int padtot = BB * padh;
    for (int j = blockIdx.x * 256 + tid; j < padtot; j += (NTOT / 8) * 256) {
        const int b_out = j / padh;
        const int t = rows + (j - b_out * padh);
        g_meta2[b_out * TX + t] = make_int2(-1, 0);
    }
}

// ---------------------------------------------------------------------------
// Kernel 3: PERSISTENT flat gather, software-pipelined. One wave (1184
// blocks); each block owns <= 3 chunks of 512 float4s. ALL chunks' meta
// loads issue up front (<= 6 int2 = 12 regs), removing one meta->x L2
// round-trip from chunks 1 and 2's critical path; x/store register
// footprint stays at one chunk (avoids the R13 ILP-4 blowup).
// ---------------------------------------------------------------------------
__global__ void __launch_bounds__(256) k_gather(const float* __restrict__ x,
                                                float* __restrict__ out) {
    const int tid = threadIdx.x;

    // per-chunk indices (pure math, before gridsync)
    int g0[MAXCH], g1[MAXCH];
    bool valid[MAXCH];
#pragma unroll
    for (int k = 0; k < MAXCH; k++) {
        const int chunk = blockIdx.x + k * PGRID;
        valid[k] = chunk < NCHUNK;
        g0[k] = chunk * 512 + tid;
        g1[k] = g0[k] + 256;
    }

    cudaGridDependencySynchronize();             // wait: g_meta2 visible

    // phase 1: ALL meta loads up front (independent)
    int2 m0[MAXCH], m1[MAXCH];
#pragma unroll
    for (int k = 0; k < MAXCH; k++) {
        if (valid[k]) {
            m0[k] = g_meta2[g0[k] / D4];
            m1[k] = g_meta2[g1[k] / D4];
        }
    }

    const float4* __restrict__ x4 = (const float4*)x;
    float4* __restrict__ o4 = (float4*)out;

    // phase 2: per-chunk x loads + lerp + store (one chunk of regs at a time)
#pragma unroll
    for (int k = 0; k < MAXCH; k++) {
        if (!valid[k]) break;                    // chunks are front-packed

        const int d40 = g0[k] - (g0[k] / D4) * D4;
        const int d41 = g1[k] - (g1[k] / D4) * D4;

        float4 r0 = make_float4(0.f, 0.f, 0.f, 0.f);
        float4 r1 = make_float4(0.f, 0.f, 0.f, 0.f);

        if (m0[k].x >= 0) {
            const int sb = m0[k].x * D4 + d40;
            const float4 a = x4[sb];
            const float4 c = x4[sb + D4];
            const float lam = __int_as_float(m0[k].y), om = 1.0f - lam;
            r0.x = om * a.x + lam * c.x;  r0.y = om * a.y + lam * c.y;
            r0.z = om * a.z + lam * c.z;  r0.w = om * a.w + lam * c.w;
        }
        if (m1[k].x >= 0) {
            const int sb = m1[k].x * D4 + d41;
            const float4 a = x4[sb];
            const float4 c = x4[sb + D4];
            const float lam = __int_as_float(m1[k].y), om = 1.0f - lam;
            r1.x = om * a.x + lam * c.x;  r1.y = om * a.y + lam * c.y;
            r1.z = om * a.z + lam * c.z;  r1.w = om * a.w + lam * c.w;
        }

        o4[g0[k]] = r0;
        o4[g1[k]] = r1;
    }
}

// ---------------------------------------------------------------------------
extern "C" void kernel_launch(void* const* d_in, const int* in_sizes, int n_in,
                              void* d_out, int out_size) {
    const float* x           = (const float*)d_in[0];  // (32, 2560, 80) f32
    const int*   len_seq     = (const int*)d_in[1];    // (32,) i32
    const float* scales_u    = (const float*)d_in[2];  // (3456,) f32
    const int*   len_seg_raw = (const int*)d_in[3];    // (3456,) i32
    float*       out         = (float*)d_out;          // (32, 2560, 80) f32

    // node 1: plain launch
    k_seg<<<BB, 32>>>(len_seq, scales_u, len_seg_raw);

    // PDL attribute: dependent grid may begin dispatch when producer triggers
    cudaLaunchAttribute attr[1];
    attr[0].id = cudaLaunchAttributeProgrammaticStreamSerialization;
    attr[0].val.programmaticStreamSerializationAllowed = 1;

    // node 2: k_rowmeta (PDL consumer of k_seg, producer for k_gather)
    {
        cudaLaunchConfig_t cfg = {};
        cfg.gridDim = dim3(NTOT / 8);
        cfg.blockDim = dim3(256);
        cfg.dynamicSmemBytes = 0;
        cfg.stream = 0;                 // legacy default stream (same as <<<>>>)
        cfg.attrs = attr;
        cfg.numAttrs = 1;
        cudaLaunchKernelEx(&cfg, k_rowmeta);
    }

    // node 3: k_gather (PDL consumer of k_rowmeta), persistent single wave
    {
        cudaLaunchConfig_t cfg = {};
        cfg.gridDim = dim3(PGRID);
        cfg.blockDim = dim3(256);
        cfg.dynamicSmemBytes = 0;
        cfg.stream = 0;
        cfg.attrs = attr;
        cfg.numAttrs = 1;
        cudaLaunchKernelEx(&cfg, k_gather, x, out);
    }
}